// round 12
// baseline (speedup 1.0000x reference)
#include <cuda_runtime.h>
#include <cuda_bf16.h>
#include <math.h>
#include <float.h>

#define Bq 256
#define Dd 128
#define NxMax 200000
#define Kn 50
#define TAUf 0.1f
#define EPSf 1e-8f
#define NTpad 1600
typedef unsigned long long ull;

// ---------------- device scratch (static; no allocs) ----------------
__device__ float g_Tq[Bq * Dd];
__device__ __nv_bfloat16 g_Tqb[Bq * Dd];
__device__ float g_tqn[Bq];
__device__ float g_xn[NxMax];
__device__ __nv_bfloat16 g_Xb[(size_t)NxMax * Dd];       // 51.2 MB bf16 X
__device__ __nv_bfloat16 g_Db[(size_t)Bq * NxMax];       // 102.4 MB bf16 distances
__device__ float g_tmin[(size_t)Bq * NTpad];             // per-(row,128-tile) min (bf16-exact)
__device__ float g_comb[512 * Dd];
__device__ float g_cn[512];
__device__ float g_Dc[512 * 512];
__device__ int   g_post[Bq * Kn];
__device__ float g_gval;
__device__ float g_acc[6];
__device__ unsigned g_h16[131072];
__device__ unsigned g_b1, g_rem1, g_b2, g_rem2;
__device__ unsigned g_minab;

// ---------------- X -> bf16 + row norms + zero accumulators ----------------
__global__ void k_convX(const float* __restrict__ X, int N) {
    int warp = threadIdx.x >> 5, lane = threadIdx.x & 31;
    if (blockIdx.x == 0 && threadIdx.x < 6) g_acc[threadIdx.x] = 0.f;
    int r = blockIdx.x * 8 + warp;
    if (r >= N) return;
    float4 v = *reinterpret_cast<const float4*>(X + (size_t)r * Dd + lane * 4);
    float s = v.x * v.x + v.y * v.y + v.z * v.z + v.w * v.w;
    __nv_bfloat162 h0 = __floats2bfloat162_rn(v.x, v.y);
    __nv_bfloat162 h1 = __floats2bfloat162_rn(v.z, v.w);
    uint2 packed;
    packed.x = *reinterpret_cast<unsigned*>(&h0);
    packed.y = *reinterpret_cast<unsigned*>(&h1);
    *reinterpret_cast<uint2*>(&g_Xb[(size_t)r * Dd + lane * 4]) = packed;
    for (int o = 16; o > 0; o >>= 1) s += __shfl_down_sync(0xffffffffu, s, o);
    if (lane == 0) g_xn[r] = s;
}

// ---------------- Tq = q @ W^T + b, norms, anchor; zero median hists ----------------
__global__ void k_tq(const float* __restrict__ q, const float* __restrict__ W,
                     const float* __restrict__ bb) {
    int i = blockIdx.x, t = threadIdx.x;
    int gid = i * 128 + t;
#pragma unroll
    for (int z = gid; z < 131072; z += 32768) g_h16[z] = 0u;
    if (gid == 0) g_minab = 0xFFFFFFFFu;
    __shared__ float qs[Dd];
    qs[t] = q[i * Dd + t];
    __syncthreads();
    const float* wr = W + t * Dd;
    float acc = bb[t];
#pragma unroll 16
    for (int c = 0; c < Dd; c++) acc = fmaf(qs[c], __ldg(&wr[c]), acc);
    g_Tq[i * Dd + t] = acc;
    g_Tqb[i * Dd + t] = __float2bfloat16(acc);
    float d = acc - qs[t];
    __shared__ float r1[Dd], r2[Dd];
    r1[t] = acc * acc; r2[t] = d * d;
    __syncthreads();
    for (int s = Dd / 2; s > 0; s >>= 1) {
        if (t < s) { r1[t] += r1[t + s]; r2[t] += r2[t + s]; }
        __syncthreads();
    }
    if (t == 0) { g_tqn[i] = r1[0]; atomicAdd(&g_acc[3], r2[0]); }
}

// ---------------- comb = [Tq ; X[idx]], norms ----------------
__global__ void k_comb(const float* __restrict__ X, const int* __restrict__ idx) {
    int i = blockIdx.x, t = threadIdx.x;
    const float* src = (i < Bq) ? (g_Tq + i * Dd) : (X + (size_t)idx[i - Bq] * Dd);
    float v = src[t];
    g_comb[i * Dd + t] = v;
    __shared__ float r1[Dd];
    r1[t] = v * v;
    __syncthreads();
    for (int s = Dd / 2; s > 0; s >>= 1) {
        if (t < s) r1[t] += r1[t + s];
        __syncthreads();
    }
    if (t == 0) g_cn[i] = r1[0];
}

// ---------------- ldmatrix helper ----------------
__device__ __forceinline__ void ldsm_x4(const void* p, unsigned& r0, unsigned& r1,
                                        unsigned& r2, unsigned& r3) {
    unsigned sa = (unsigned)__cvta_generic_to_shared(p);
    asm volatile("ldmatrix.sync.aligned.m8n8.x4.shared.b16 {%0,%1,%2,%3}, [%4];"
                 : "=r"(r0), "=r"(r1), "=r"(r2), "=r"(r3) : "r"(sa));
}

// ---------------- bf16 tensor-core distance GEMM: Db + tile mins ----------------
#define SSTR 72
#define DSTR 136
__global__ void __launch_bounds__(256) k_gemm(int N) {
    __shared__ __align__(16) __nv_bfloat16 sm[2 * 128 * SSTR];
    __shared__ float tns[128], xns[128];
    __shared__ unsigned minu[128];
    __nv_bfloat16* smA = sm;
    __nv_bfloat16* smB = sm + 128 * SSTR;
    int m0 = blockIdx.x * 128;                     // x = m-panel -> tile pairing in L2
    int n0 = blockIdx.y * 128;
    int tile = blockIdx.y;
    int tid = threadIdx.x;
    int warp = tid >> 5, lane = tid & 31;
    int g = lane >> 2, tg = lane & 3;
    int wm = (warp >> 1) * 32;
    int wn = (warp & 1) * 64;
    int rowoff = (lane & 7) + ((lane >> 3) & 1) * 8;
    int koff = (lane >> 4) * 8;
    float acc[2][8][4];
#pragma unroll
    for (int i = 0; i < 2; i++)
#pragma unroll
        for (int j = 0; j < 8; j++)
#pragma unroll
            for (int e = 0; e < 4; e++) acc[i][j][e] = 0.f;

    uint4 pa0[4], pb0[4], pa1[4], pb1[4];
#pragma unroll
    for (int u = 0; u < 4; u++) {
        int s = tid + u * 256;
        int r = s >> 3, c = (s & 7) * 8;
        pa0[u] = *reinterpret_cast<const uint4*>(&g_Tqb[(m0 + r) * Dd + c]);
        pa1[u] = *reinterpret_cast<const uint4*>(&g_Tqb[(m0 + r) * Dd + 64 + c]);
        int n = n0 + r;
        uint4 z = make_uint4(0u, 0u, 0u, 0u);
        pb0[u] = z; pb1[u] = z;
        if (n < N) {
            const __nv_bfloat16* bp = &g_Xb[(size_t)n * Dd];
            pb0[u] = *reinterpret_cast<const uint4*>(&bp[c]);
            pb1[u] = *reinterpret_cast<const uint4*>(&bp[64 + c]);
        }
    }
    if (tid < 128) {
        tns[tid] = g_tqn[m0 + tid];
        int n = n0 + tid;
        xns[tid] = (n < N) ? g_xn[n] : 0.f;
        minu[tid] = 0x7f7fffffu;                   // FLT_MAX
    }

#pragma unroll
    for (int st = 0; st < 2; st++) {
#pragma unroll
        for (int u = 0; u < 4; u++) {
            int s = tid + u * 256;
            int r = s >> 3, c = (s & 7) * 8;
            *reinterpret_cast<uint4*>(&smA[r * SSTR + c]) = st ? pa1[u] : pa0[u];
            *reinterpret_cast<uint4*>(&smB[r * SSTR + c]) = st ? pb1[u] : pb0[u];
        }
        __syncthreads();
#pragma unroll
        for (int ks = 0; ks < 64; ks += 16) {
            unsigned a[2][4], bb[4][4];
#pragma unroll
            for (int i = 0; i < 2; i++)
                ldsm_x4(&smA[(wm + i * 16 + rowoff) * SSTR + ks + koff],
                        a[i][0], a[i][1], a[i][2], a[i][3]);
#pragma unroll
            for (int jp = 0; jp < 4; jp++)
                ldsm_x4(&smB[(wn + jp * 16 + rowoff) * SSTR + ks + koff],
                        bb[jp][0], bb[jp][1], bb[jp][2], bb[jp][3]);
#pragma unroll
            for (int i = 0; i < 2; i++)
#pragma unroll
                for (int j = 0; j < 8; j++) {
                    unsigned b0 = bb[j >> 1][j & 1];
                    unsigned b1 = bb[j >> 1][2 + (j & 1)];
                    asm volatile(
                        "mma.sync.aligned.m16n8k16.row.col.f32.bf16.bf16.f32 "
                        "{%0,%1,%2,%3}, {%4,%5,%6,%7}, {%8,%9}, {%0,%1,%2,%3};"
                        : "+f"(acc[i][j][0]), "+f"(acc[i][j][1]),
                          "+f"(acc[i][j][2]), "+f"(acc[i][j][3])
                        : "r"(a[i][0]), "r"(a[i][1]), "r"(a[i][2]), "r"(a[i][3]),
                          "r"(b0), "r"(b1));
                }
        }
        __syncthreads();
    }

    // epilogue: bf16 d2 into smem overlay; per-row min of the SAME bf16 values
    __nv_bfloat16* Ds = sm;                        // 128*DSTR = 17408 <= 18432 elems
#pragma unroll
    for (int i = 0; i < 2; i++) {
        int r0 = wm + i * 16 + g, r1 = r0 + 8;
        float tn0 = tns[r0], tn1 = tns[r1];
        float rm0 = FLT_MAX, rm1 = FLT_MAX;
#pragma unroll
        for (int j = 0; j < 8; j++) {
            int cl = wn + j * 8 + tg * 2;
            int n = n0 + cl;
            if (n < N) {                           // N even -> n+1 < N
                float xa = xns[cl], xb = xns[cl + 1];
                float d00 = fmaxf(tn0 + xa - 2.f * acc[i][j][0], 0.f);
                float d01 = fmaxf(tn0 + xb - 2.f * acc[i][j][1], 0.f);
                float d10 = fmaxf(tn1 + xa - 2.f * acc[i][j][2], 0.f);
                float d11 = fmaxf(tn1 + xb - 2.f * acc[i][j][3], 0.f);
                __nv_bfloat162 p0 = __floats2bfloat162_rn(d00, d01);
                __nv_bfloat162 p1 = __floats2bfloat162_rn(d10, d11);
                float2 f0 = __bfloat1622float2(p0);
                float2 f1 = __bfloat1622float2(p1);
                rm0 = fminf(rm0, fminf(f0.x, f0.y));
                rm1 = fminf(rm1, fminf(f1.x, f1.y));
                *reinterpret_cast<unsigned*>(&Ds[r0 * DSTR + cl]) =
                    *reinterpret_cast<unsigned*>(&p0);
                *reinterpret_cast<unsigned*>(&Ds[r1 * DSTR + cl]) =
                    *reinterpret_cast<unsigned*>(&p1);
            }
        }
        rm0 = fminf(rm0, __shfl_xor_sync(0xffffffffu, rm0, 1));
        rm0 = fminf(rm0, __shfl_xor_sync(0xffffffffu, rm0, 2));
        rm1 = fminf(rm1, __shfl_xor_sync(0xffffffffu, rm1, 1));
        rm1 = fminf(rm1, __shfl_xor_sync(0xffffffffu, rm1, 2));
        if (tg == 0) {
            atomicMin(&minu[r0], __float_as_uint(rm0));
            atomicMin(&minu[r1], __float_as_uint(rm1));
        }
    }
    __syncthreads();
    // coalesced drain of Db
#pragma unroll
    for (int task = tid; task < 2048; task += 256) {
        int r = task >> 4, c = task & 15;
        int n = n0 + c * 8;
        if (n < N)                                  // N % 8 == 0 -> full uint4 valid
            *reinterpret_cast<uint4*>(&g_Db[(size_t)(m0 + r) * N + n]) =
                *reinterpret_cast<const uint4*>(&Ds[r * DSTR + c * 8]);
    }
    if (tid < 128)
        g_tmin[(size_t)(m0 + tid) * NTpad + tile] = __uint_as_float(minu[tid]);
}

// ---------------- Dc = sqdist(comb, comb), 32x32 tiles; fused hi16 histogram ----------
#define DCS 36
__global__ void __launch_bounds__(256) k_dc2() {
    __shared__ float AsT[128][DCS];
    __shared__ float BsT[128][DCS];
    int i0 = blockIdx.y * 32, j0 = blockIdx.x * 32;
    int tid = threadIdx.x;
#pragma unroll
    for (int s = tid; s < 1024; s += 256) {
        int k = s & 127, r4 = (s >> 7) * 4;
        float4 va, vb;
        va.x = g_comb[(i0 + r4 + 0) * Dd + k];
        va.y = g_comb[(i0 + r4 + 1) * Dd + k];
        va.z = g_comb[(i0 + r4 + 2) * Dd + k];
        va.w = g_comb[(i0 + r4 + 3) * Dd + k];
        *reinterpret_cast<float4*>(&AsT[k][r4]) = va;
        vb.x = g_comb[(j0 + r4 + 0) * Dd + k];
        vb.y = g_comb[(j0 + r4 + 1) * Dd + k];
        vb.z = g_comb[(j0 + r4 + 2) * Dd + k];
        vb.w = g_comb[(j0 + r4 + 3) * Dd + k];
        *reinterpret_cast<float4*>(&BsT[k][r4]) = vb;
    }
    __syncthreads();
    int tr = tid >> 4, tc = tid & 15;
    float a00 = 0.f, a01 = 0.f, a10 = 0.f, a11 = 0.f;
#pragma unroll 8
    for (int k = 0; k < 128; k++) {
        float2 a = *reinterpret_cast<const float2*>(&AsT[k][tr * 2]);
        float2 b = *reinterpret_cast<const float2*>(&BsT[k][tc * 2]);
        a00 = fmaf(a.x, b.x, a00); a01 = fmaf(a.x, b.y, a01);
        a10 = fmaf(a.y, b.x, a10); a11 = fmaf(a.y, b.y, a11);
    }
    int ri = i0 + tr * 2, rj = j0 + tc * 2;
    float ci0 = g_cn[ri], ci1 = g_cn[ri + 1], cj0 = g_cn[rj], cj1 = g_cn[rj + 1];
    float v00 = fmaxf(ci0 + cj0 - 2.f * a00, 0.f);
    float v01 = fmaxf(ci0 + cj1 - 2.f * a01, 0.f);
    float v10 = fmaxf(ci1 + cj0 - 2.f * a10, 0.f);
    float v11 = fmaxf(ci1 + cj1 - 2.f * a11, 0.f);
    g_Dc[ri * 512 + rj] = v00;       g_Dc[ri * 512 + rj + 1] = v01;
    g_Dc[(ri + 1) * 512 + rj] = v10; g_Dc[(ri + 1) * 512 + rj + 1] = v11;
    atomicAdd(&g_h16[__float_as_uint(v00) >> 16], 1u);
    atomicAdd(&g_h16[__float_as_uint(v01) >> 16], 1u);
    atomicAdd(&g_h16[__float_as_uint(v10) >> 16], 1u);
    atomicAdd(&g_h16[__float_as_uint(v11) >> 16], 1u);
}

// ---------------- decide hi16 buckets for ranks 131072, 131073 ----------------
__global__ void __launch_bounds__(1024) k_decide16() {
    __shared__ unsigned s[1024];
    int t = threadIdx.x;
    unsigned part = 0;
#pragma unroll 8
    for (int i = 0; i < 64; i++) part += g_h16[t * 64 + i];
    s[t] = part;
    __syncthreads();
    for (int off = 1; off < 1024; off <<= 1) {
        unsigned v = (t >= off) ? s[t - off] : 0u;
        __syncthreads();
        s[t] += v;
        __syncthreads();
    }
    unsigned before = (t > 0) ? s[t - 1] : 0u;
    unsigned after = s[t];
#pragma unroll
    for (int which = 0; which < 2; which++) {
        unsigned rank = 131072u + (unsigned)which;
        if (before < rank && rank <= after) {
            unsigned cum = before;
            for (int i = 0; i < 64; i++) {
                unsigned c = g_h16[t * 64 + i];
                if (cum + c >= rank) {
                    if (which == 0) { g_b1 = (unsigned)(t * 64 + i); g_rem1 = rank - cum; }
                    else            { g_b2 = (unsigned)(t * 64 + i); g_rem2 = rank - cum; }
                    break;
                }
                cum += c;
            }
        }
    }
}

// ---------------- lo16 histogram within bucket b1; min lo16 in bucket b2 ----------------
__global__ void k_histlow() {
    unsigned b1 = g_b1, b2 = g_b2;
    unsigned lm = 0xFFFFFFFFu;
    for (int id = blockIdx.x * blockDim.x + threadIdx.x; id < 512 * 512;
         id += gridDim.x * blockDim.x) {
        unsigned u = __float_as_uint(g_Dc[id]);
        unsigned hi = u >> 16;
        if (hi == b1) atomicAdd(&g_h16[65536 + (u & 0xFFFFu)], 1u);
        else if (hi == b2) lm = min(lm, u & 0xFFFFu);
    }
    for (int o = 16; o > 0; o >>= 1) lm = min(lm, __shfl_down_sync(0xffffffffu, lm, o));
    __shared__ unsigned sm[8];
    int w = threadIdx.x >> 5;
    if ((threadIdx.x & 31) == 0) sm[w] = lm;
    __syncthreads();
    if (threadIdx.x == 0) {
        unsigned m = sm[0];
        for (int i = 1; i < 8; i++) m = min(m, sm[i]);
        if (m != 0xFFFFFFFFu) atomicMin(&g_minab, m);
    }
}

// ---------------- decide lo16, compute gamma ----------------
__global__ void __launch_bounds__(1024) k_decidelow() {
    __shared__ unsigned s[1024];
    __shared__ unsigned shv[2];
    int t = threadIdx.x;
    unsigned part = 0;
#pragma unroll 8
    for (int i = 0; i < 64; i++) part += g_h16[65536 + t * 64 + i];
    s[t] = part;
    __syncthreads();
    for (int off = 1; off < 1024; off <<= 1) {
        unsigned v = (t >= off) ? s[t - off] : 0u;
        __syncthreads();
        s[t] += v;
        __syncthreads();
    }
    unsigned before = (t > 0) ? s[t - 1] : 0u;
    unsigned after = s[t];
    unsigned b1 = g_b1, b2 = g_b2;
    bool same = (b1 == b2);
    unsigned ranks[2] = { g_rem1, same ? g_rem2 : 0u };
#pragma unroll
    for (int which = 0; which < 2; which++) {
        if (which == 1 && !same) break;
        unsigned rank = ranks[which];
        if (before < rank && rank <= after) {
            unsigned cum = before;
            for (int i = 0; i < 64; i++) {
                unsigned c = g_h16[65536 + t * 64 + i];
                if (cum + c >= rank) { shv[which] = (unsigned)(t * 64 + i); break; }
                cum += c;
            }
        }
    }
    __syncthreads();
    if (t == 0) {
        unsigned v1 = (b1 << 16) | shv[0];
        unsigned v2 = same ? ((b1 << 16) | shv[1]) : ((b2 << 16) | g_minab);
        float med = 0.5f * (__uint_as_float(v1) + __uint_as_float(v2));
        float sig = med * 0.5f;
        if (sig < 1e-6f) sig = 1.0f;
        g_gval = 1.0f / (sig + EPSf);
    }
}

// ---------------- MMD kernel sums ----------------
__global__ void k_mmd() {
    float g = g_gval;
    float sxx = 0.f, syy = 0.f, sxy = 0.f;
    for (int id = blockIdx.x * blockDim.x + threadIdx.x; id < 512 * 512;
         id += gridDim.x * blockDim.x) {
        int i = id >> 9, j = id & 511;
        float e = expf(-g * g_Dc[id]);
        if (i < Bq) { if (j < Bq) sxx += e; else sxy += e; }
        else if (j >= Bq) syy += e;
    }
    __shared__ float s1[256], s2[256], s3[256];
    int t = threadIdx.x;
    s1[t] = sxx; s2[t] = syy; s3[t] = sxy;
    __syncthreads();
    for (int s = 128; s > 0; s >>= 1) {
        if (t < s) { s1[t] += s1[t + s]; s2[t] += s2[t + s]; s3[t] += s3[t + s]; }
        __syncthreads();
    }
    if (t == 0) {
        atomicAdd(&g_acc[0], s1[0]);
        atomicAdd(&g_acc[1], s2[0]);
        atomicAdd(&g_acc[2], s3[0]);
    }
}

// ---------------- top-50: sorted tile-min guided scan over Db (exact, no margin) ----
__device__ __forceinline__ void bitonic2048(ull* a, int tid) {
    for (int k = 2; k <= 2048; k <<= 1) {
        for (int j = k >> 1; j > 0; j >>= 1) {
#pragma unroll
            for (int u = 0; u < 4; u++) {
                int i = tid + u * 512;
                int ixj = i ^ j;
                if (ixj > i) {
                    bool up = ((i & k) == 0);
                    ull x = a[i], y = a[ixj];
                    if ((x > y) == up) { a[i] = y; a[ixj] = x; }
                }
            }
            __syncthreads();
        }
    }
}

__global__ void __launch_bounds__(512) k_topk(int N) {
    __shared__ ull tiles[2048];
    __shared__ ull cand[2048];
    __shared__ int cnt;
    __shared__ float curT;
    int row = blockIdx.x, tid = threadIdx.x;
    int NT = (N + 127) >> 7;
    for (int t = tid; t < 2048; t += 512) {
        tiles[t] = (t < NT)
            ? ((((ull)__float_as_uint(g_tmin[(size_t)row * NTpad + t])) << 32) | (unsigned)t)
            : ~0ull;
        cand[t] = ~0ull;
    }
    if (tid == 0) cnt = Kn;
    __syncthreads();
    bitonic2048(tiles, tid);                       // ascending (min, tile)
    const __nv_bfloat16* Drow = g_Db + (size_t)row * N;
    int slot = tid >> 7, col = tid & 127;

    // seed: 8 lowest-min tiles, unconditional (coalesced 256B per tile)
#pragma unroll
    for (int s0 = 0; s0 < 8; s0 += 4) {
        int s = s0 + slot;
        int tl = (int)(tiles[s] & 0xFFFFFFFFu);
        int n = tl * 128 + col;
        if (n < N) {
            float v = __bfloat162float(Drow[n]);
            cand[s * 128 + col] = (((ull)__float_as_uint(v)) << 32) | (unsigned)n;
        }
    }
    __syncthreads();
    bitonic2048(cand, tid);
    if (tid == 0) curT = __uint_as_float((unsigned)(cand[Kn - 1] >> 32));
    __syncthreads();
    for (int i = Kn + tid; i < 2048; i += 512) cand[i] = ~0ull;
    __syncthreads();

    for (int s0 = 8; s0 < NT; s0 += 4) {
        float T = curT;
        if (__uint_as_float((unsigned)(tiles[s0] >> 32)) > T) break;   // exact bound
        int s = s0 + slot;
        if (s < NT) {
            ull key = tiles[s];
            if (__uint_as_float((unsigned)(key >> 32)) <= T) {
                int tl = (int)(key & 0xFFFFFFFFu);
                int n = tl * 128 + col;
                if (n < N) {
                    float v = __bfloat162float(Drow[n]);
                    if (v <= T) {
                        int p = atomicAdd(&cnt, 1);
                        cand[p] = (((ull)__float_as_uint(v)) << 32) | (unsigned)n;
                    }
                }
            }
        }
        __syncthreads();
        if (cnt >= 1536) {                          // max 1535+512=2047 < 2048: safe
            bitonic2048(cand, tid);
            if (tid == 0) {
                curT = __uint_as_float((unsigned)(cand[Kn - 1] >> 32));
                cnt = Kn;
            }
            __syncthreads();
            for (int i = Kn + tid; i < 2048; i += 512) cand[i] = ~0ull;
            __syncthreads();
        }
    }
    bitonic2048(cand, tid);
    if (tid < Kn) g_post[row * Kn + tid] = (int)(cand[tid] & 0xFFFFFFFFu);
}

// ---------------- union-KL per row (exact fp32) ----------------
__global__ void k_kl(const float* __restrict__ X, const float* __restrict__ pw,
                     const int* __restrict__ pi, const int* __restrict__ qind) {
    int row = blockIdx.x, t = threadIdx.x;
    __shared__ float Tqs[Dd];
    __shared__ int cat[2 * Kn];
    __shared__ float prew[Kn], postw[Kn], l2s[Kn];
    __shared__ float pm[2 * Kn], qm[2 * Kn], mlt[2 * Kn];
    __shared__ float red[Dd];
    __shared__ float Sp, Sq;
    Tqs[t] = g_Tq[row * Dd + t];
    int qi = qind[row];
    if (t < Kn) {
        cat[t] = pi[qi * Kn + t];
        prew[t] = pw[qi * Kn + t];
        cat[Kn + t] = g_post[row * Kn + t];
    }
    __syncthreads();
    int warp = t >> 5, lane = t & 31;
    for (int k = warp; k < Kn; k += 4) {
        const float* xr = X + (size_t)cat[Kn + k] * Dd;
        float s = 0.f;
#pragma unroll
        for (int c = lane; c < Dd; c += 32) {
            float d = Tqs[c] - xr[c];
            s = fmaf(d, d, s);
        }
        for (int o = 16; o > 0; o >>= 1) s += __shfl_down_sync(0xffffffffu, s, o);
        if (lane == 0) l2s[k] = s;
    }
    __syncthreads();
    if (t == 0) {
        float mx = -FLT_MAX;
        for (int k = 0; k < Kn; k++) {
            float z = -l2s[k] * (1.f / TAUf);
            if (z > mx) mx = z;
        }
        float sm = 0.f;
        for (int k = 0; k < Kn; k++) {
            float e = expf(-l2s[k] * (1.f / TAUf) - mx);
            postw[k] = e; sm += e;
        }
        float inv = 1.f / sm;
        for (int k = 0; k < Kn; k++) postw[k] *= inv;
    }
    __syncthreads();
    if (t < 2 * Kn) {
        int id = cat[t];
        int m = 0; float pr = 0.f, qr = 0.f;
        for (int k = 0; k < 2 * Kn; k++) m += (cat[k] == id);
        for (int k = 0; k < Kn; k++) {
            if (cat[k] == id) pr += prew[k];
            if (cat[Kn + k] == id) qr += postw[k];
        }
        pm[t] = fmaxf(pr, EPSf); qm[t] = fmaxf(qr, EPSf); mlt[t] = (float)m;
    }
    __syncthreads();
    if (t == 0) {
        float a = 0.f, bs = 0.f;
        for (int m2 = 0; m2 < 2 * Kn; m2++) { a += pm[m2] / mlt[m2]; bs += qm[m2] / mlt[m2]; }
        Sp = a; Sq = bs;
    }
    __syncthreads();
    float klc = 0.f;
    if (t < 2 * Kn) {
        float p = pm[t] / Sp, q2 = qm[t] / Sq;
        klc = p * (logf(p) - logf(q2)) / mlt[t];
    }
    red[t] = klc;
    __syncthreads();
    for (int s = Dd / 2; s > 0; s >>= 1) {
        if (t < s) red[t] += red[t + s];
        __syncthreads();
    }
    if (t == 0) atomicAdd(&g_acc[4], red[0]);
}

// ---------------- finalize ----------------
__global__ void k_final(const float* __restrict__ W, const float* __restrict__ b,
                        float* __restrict__ out) {
    __shared__ float red[256];
    int t = threadIdx.x;
    float s = 0.f;
    for (int i = t; i < Dd * Dd; i += 256) { float w = W[i]; s = fmaf(w, w, s); }
    if (t < Dd) { float bv = b[t]; s = fmaf(bv, bv, s); }
    red[t] = s;
    __syncthreads();
    for (int st = 128; st > 0; st >>= 1) {
        if (t < st) red[t] += red[t + st];
        __syncthreads();
    }
    if (t == 0) {
        float reg = 0.5f * red[0];
        float inv = 1.0f / 65536.0f;
        float kxx = g_acc[0] * inv, kyy = g_acc[1] * inv, kxy = g_acc[2] * inv;
        float dist = fmaxf(kxx + kyy - 2.f * kxy, 0.f);
        float knn = g_acc[4] / 256.0f;
        float anchor = g_acc[3] / 256.0f;
        float total = dist + knn + 1e-4f * reg + anchor;
        out[0] = total; out[1] = dist; out[2] = knn; out[3] = anchor;
    }
}

// ---------------- launch ----------------
extern "C" void kernel_launch(void* const* d_in, const int* in_sizes, int n_in,
                              void* d_out, int out_size) {
    const float* q  = (const float*)d_in[0];
    const float* X  = (const float*)d_in[1];
    const float* W  = (const float*)d_in[2];
    const float* b  = (const float*)d_in[3];
    const float* pw = (const float*)d_in[4];
    const int* pi   = (const int*)d_in[5];
    const int* qi   = (const int*)d_in[6];
    const int* idx  = (const int*)d_in[7];
    int N = in_sizes[1] / Dd;                       // 200000
    if (N > NxMax) N = NxMax;
    int NT = (N + 127) / 128;

    k_convX<<<(N + 7) / 8, 256>>>(X, N);
    k_tq<<<Bq, Dd>>>(q, W, b);
    k_comb<<<512, Dd>>>(X, idx);
    dim3 gg(Bq / 128, NT);
    k_gemm<<<gg, 256>>>(N);                         // 4th launch -> ncu capture
    k_topk<<<Bq, 512>>>(N);
    dim3 dg(512 / 32, 512 / 32);
    k_dc2<<<dg, 256>>>();
    k_decide16<<<1, 1024>>>();
    k_histlow<<<256, 256>>>();
    k_decidelow<<<1, 1024>>>();
    k_mmd<<<512, 256>>>();
    k_kl<<<Bq, Dd>>>(X, pw, pi, qi);
    k_final<<<1, 256>>>(W, b, (float*)d_out);
}

// round 13
// speedup vs baseline: 1.0083x; 1.0083x over previous
#include <cuda_runtime.h>
#include <cuda_bf16.h>
#include <math.h>
#include <float.h>

#define Bq 256
#define Dd 128
#define NxMax 200000
#define Kn 50
#define TAUf 0.1f
#define EPSf 1e-8f
#define NTpad 1600
typedef unsigned long long ull;

// ---------------- device scratch (static; no allocs) ----------------
__device__ float g_Tq[Bq * Dd];
__device__ __nv_bfloat16 g_Tqb[Bq * Dd];
__device__ float g_tqn[Bq];
__device__ float g_xn[NxMax];
__device__ __nv_bfloat16 g_Xb[(size_t)NxMax * Dd];       // 51.2 MB bf16 X
__device__ __nv_bfloat16 g_Db[(size_t)Bq * NxMax];       // 102.4 MB bf16 distances
__device__ float g_tmin[(size_t)Bq * NTpad];             // per-(row,128-tile) min (bf16-exact)
__device__ float g_comb[512 * Dd];
__device__ float g_cn[512];
__device__ float g_Dc[512 * 512];
__device__ int   g_post[Bq * Kn];
__device__ float g_gval;
__device__ float g_acc[6];
__device__ unsigned g_h16[131072];
__device__ unsigned g_b1, g_rem1, g_b2, g_rem2;
__device__ unsigned g_minab;

// ---------------- X -> bf16 + row norms + zero accumulators ----------------
__global__ void k_convX(const float* __restrict__ X, int N) {
    int warp = threadIdx.x >> 5, lane = threadIdx.x & 31;
    if (blockIdx.x == 0 && threadIdx.x < 6) g_acc[threadIdx.x] = 0.f;
    int r = blockIdx.x * 8 + warp;
    if (r >= N) return;
    float4 v = *reinterpret_cast<const float4*>(X + (size_t)r * Dd + lane * 4);
    float s = v.x * v.x + v.y * v.y + v.z * v.z + v.w * v.w;
    __nv_bfloat162 h0 = __floats2bfloat162_rn(v.x, v.y);
    __nv_bfloat162 h1 = __floats2bfloat162_rn(v.z, v.w);
    uint2 packed;
    packed.x = *reinterpret_cast<unsigned*>(&h0);
    packed.y = *reinterpret_cast<unsigned*>(&h1);
    *reinterpret_cast<uint2*>(&g_Xb[(size_t)r * Dd + lane * 4]) = packed;
    for (int o = 16; o > 0; o >>= 1) s += __shfl_down_sync(0xffffffffu, s, o);
    if (lane == 0) g_xn[r] = s;
}

// ---------------- Tq = q @ W^T + b, norms, anchor; zero median hists ----------------
__global__ void k_tq(const float* __restrict__ q, const float* __restrict__ W,
                     const float* __restrict__ bb) {
    int i = blockIdx.x, t = threadIdx.x;
    int gid = i * 128 + t;
#pragma unroll
    for (int z = gid; z < 131072; z += 32768) g_h16[z] = 0u;
    if (gid == 0) g_minab = 0xFFFFFFFFu;
    __shared__ float qs[Dd];
    qs[t] = q[i * Dd + t];
    __syncthreads();
    const float* wr = W + t * Dd;
    float acc = bb[t];
#pragma unroll 16
    for (int c = 0; c < Dd; c++) acc = fmaf(qs[c], __ldg(&wr[c]), acc);
    g_Tq[i * Dd + t] = acc;
    g_Tqb[i * Dd + t] = __float2bfloat16(acc);
    float d = acc - qs[t];
    __shared__ float r1[Dd], r2[Dd];
    r1[t] = acc * acc; r2[t] = d * d;
    __syncthreads();
    for (int s = Dd / 2; s > 0; s >>= 1) {
        if (t < s) { r1[t] += r1[t + s]; r2[t] += r2[t + s]; }
        __syncthreads();
    }
    if (t == 0) { g_tqn[i] = r1[0]; atomicAdd(&g_acc[3], r2[0]); }
}

// ---------------- comb = [Tq ; X[idx]], norms ----------------
__global__ void k_comb(const float* __restrict__ X, const int* __restrict__ idx) {
    int i = blockIdx.x, t = threadIdx.x;
    const float* src = (i < Bq) ? (g_Tq + i * Dd) : (X + (size_t)idx[i - Bq] * Dd);
    float v = src[t];
    g_comb[i * Dd + t] = v;
    __shared__ float r1[Dd];
    r1[t] = v * v;
    __syncthreads();
    for (int s = Dd / 2; s > 0; s >>= 1) {
        if (t < s) r1[t] += r1[t + s];
        __syncthreads();
    }
    if (t == 0) g_cn[i] = r1[0];
}

// ---------------- ldmatrix helper ----------------
__device__ __forceinline__ void ldsm_x4(const void* p, unsigned& r0, unsigned& r1,
                                        unsigned& r2, unsigned& r3) {
    unsigned sa = (unsigned)__cvta_generic_to_shared(p);
    asm volatile("ldmatrix.sync.aligned.m8n8.x4.shared.b16 {%0,%1,%2,%3}, [%4];"
                 : "=r"(r0), "=r"(r1), "=r"(r2), "=r"(r3) : "r"(sa));
}

// ---------------- bf16 tensor-core distance GEMM: Db + tile mins ----------------
#define SSTR 72
#define DSTR 136
__global__ void __launch_bounds__(256) k_gemm(int N) {
    __shared__ __align__(16) __nv_bfloat16 sm[2 * 128 * SSTR];
    __shared__ float tns[128], xns[128];
    __shared__ unsigned minu[128];
    __nv_bfloat16* smA = sm;
    __nv_bfloat16* smB = sm + 128 * SSTR;
    int m0 = blockIdx.x * 128;                     // x = m-panel -> tile pairing in L2
    int n0 = blockIdx.y * 128;
    int tile = blockIdx.y;
    int tid = threadIdx.x;
    int warp = tid >> 5, lane = tid & 31;
    int g = lane >> 2, tg = lane & 3;
    int wm = (warp >> 1) * 32;
    int wn = (warp & 1) * 64;
    int rowoff = (lane & 7) + ((lane >> 3) & 1) * 8;
    int koff = (lane >> 4) * 8;
    float acc[2][8][4];
#pragma unroll
    for (int i = 0; i < 2; i++)
#pragma unroll
        for (int j = 0; j < 8; j++)
#pragma unroll
            for (int e = 0; e < 4; e++) acc[i][j][e] = 0.f;

    uint4 pa0[4], pb0[4], pa1[4], pb1[4];
#pragma unroll
    for (int u = 0; u < 4; u++) {
        int s = tid + u * 256;
        int r = s >> 3, c = (s & 7) * 8;
        pa0[u] = *reinterpret_cast<const uint4*>(&g_Tqb[(m0 + r) * Dd + c]);
        pa1[u] = *reinterpret_cast<const uint4*>(&g_Tqb[(m0 + r) * Dd + 64 + c]);
        int n = n0 + r;
        uint4 z = make_uint4(0u, 0u, 0u, 0u);
        pb0[u] = z; pb1[u] = z;
        if (n < N) {
            const __nv_bfloat16* bp = &g_Xb[(size_t)n * Dd];
            pb0[u] = *reinterpret_cast<const uint4*>(&bp[c]);
            pb1[u] = *reinterpret_cast<const uint4*>(&bp[64 + c]);
        }
    }
    if (tid < 128) {
        tns[tid] = g_tqn[m0 + tid];
        int n = n0 + tid;
        xns[tid] = (n < N) ? g_xn[n] : 0.f;
        minu[tid] = 0x7f7fffffu;                   // FLT_MAX
    }

#pragma unroll
    for (int st = 0; st < 2; st++) {
#pragma unroll
        for (int u = 0; u < 4; u++) {
            int s = tid + u * 256;
            int r = s >> 3, c = (s & 7) * 8;
            *reinterpret_cast<uint4*>(&smA[r * SSTR + c]) = st ? pa1[u] : pa0[u];
            *reinterpret_cast<uint4*>(&smB[r * SSTR + c]) = st ? pb1[u] : pb0[u];
        }
        __syncthreads();
#pragma unroll
        for (int ks = 0; ks < 64; ks += 16) {
            unsigned a[2][4], bb[4][4];
#pragma unroll
            for (int i = 0; i < 2; i++)
                ldsm_x4(&smA[(wm + i * 16 + rowoff) * SSTR + ks + koff],
                        a[i][0], a[i][1], a[i][2], a[i][3]);
#pragma unroll
            for (int jp = 0; jp < 4; jp++)
                ldsm_x4(&smB[(wn + jp * 16 + rowoff) * SSTR + ks + koff],
                        bb[jp][0], bb[jp][1], bb[jp][2], bb[jp][3]);
#pragma unroll
            for (int i = 0; i < 2; i++)
#pragma unroll
                for (int j = 0; j < 8; j++) {
                    unsigned b0 = bb[j >> 1][j & 1];
                    unsigned b1 = bb[j >> 1][2 + (j & 1)];
                    asm volatile(
                        "mma.sync.aligned.m16n8k16.row.col.f32.bf16.bf16.f32 "
                        "{%0,%1,%2,%3}, {%4,%5,%6,%7}, {%8,%9}, {%0,%1,%2,%3};"
                        : "+f"(acc[i][j][0]), "+f"(acc[i][j][1]),
                          "+f"(acc[i][j][2]), "+f"(acc[i][j][3])
                        : "r"(a[i][0]), "r"(a[i][1]), "r"(a[i][2]), "r"(a[i][3]),
                          "r"(b0), "r"(b1));
                }
        }
        __syncthreads();
    }

    // epilogue: bf16 d2 into smem overlay; per-row min of the SAME bf16 values
    __nv_bfloat16* Ds = sm;                        // 128*DSTR = 17408 <= 18432 elems
#pragma unroll
    for (int i = 0; i < 2; i++) {
        int r0 = wm + i * 16 + g, r1 = r0 + 8;
        float tn0 = tns[r0], tn1 = tns[r1];
        float rm0 = FLT_MAX, rm1 = FLT_MAX;
#pragma unroll
        for (int j = 0; j < 8; j++) {
            int cl = wn + j * 8 + tg * 2;
            int n = n0 + cl;
            if (n < N) {                           // N even -> n+1 < N
                float xa = xns[cl], xb = xns[cl + 1];
                float d00 = fmaxf(tn0 + xa - 2.f * acc[i][j][0], 0.f);
                float d01 = fmaxf(tn0 + xb - 2.f * acc[i][j][1], 0.f);
                float d10 = fmaxf(tn1 + xa - 2.f * acc[i][j][2], 0.f);
                float d11 = fmaxf(tn1 + xb - 2.f * acc[i][j][3], 0.f);
                __nv_bfloat162 p0 = __floats2bfloat162_rn(d00, d01);
                __nv_bfloat162 p1 = __floats2bfloat162_rn(d10, d11);
                float2 f0 = __bfloat1622float2(p0);
                float2 f1 = __bfloat1622float2(p1);
                rm0 = fminf(rm0, fminf(f0.x, f0.y));
                rm1 = fminf(rm1, fminf(f1.x, f1.y));
                *reinterpret_cast<unsigned*>(&Ds[r0 * DSTR + cl]) =
                    *reinterpret_cast<unsigned*>(&p0);
                *reinterpret_cast<unsigned*>(&Ds[r1 * DSTR + cl]) =
                    *reinterpret_cast<unsigned*>(&p1);
            }
        }
        rm0 = fminf(rm0, __shfl_xor_sync(0xffffffffu, rm0, 1));
        rm0 = fminf(rm0, __shfl_xor_sync(0xffffffffu, rm0, 2));
        rm1 = fminf(rm1, __shfl_xor_sync(0xffffffffu, rm1, 1));
        rm1 = fminf(rm1, __shfl_xor_sync(0xffffffffu, rm1, 2));
        if (tg == 0) {
            atomicMin(&minu[r0], __float_as_uint(rm0));
            atomicMin(&minu[r1], __float_as_uint(rm1));
        }
    }
    __syncthreads();
    // coalesced drain of Db
#pragma unroll
    for (int task = tid; task < 2048; task += 256) {
        int r = task >> 4, c = task & 15;
        int n = n0 + c * 8;
        if (n < N)                                  // N % 8 == 0 -> full uint4 valid
            *reinterpret_cast<uint4*>(&g_Db[(size_t)(m0 + r) * N + n]) =
                *reinterpret_cast<const uint4*>(&Ds[r * DSTR + c * 8]);
    }
    if (tid < 128)
        g_tmin[(size_t)(m0 + tid) * NTpad + tile] = __uint_as_float(minu[tid]);
}

// ---------------- Dc = sqdist(comb, comb), 32x32 tiles; fused hi16 histogram ----------
#define DCS 36
__global__ void __launch_bounds__(256) k_dc2() {
    __shared__ float AsT[128][DCS];
    __shared__ float BsT[128][DCS];
    int i0 = blockIdx.y * 32, j0 = blockIdx.x * 32;
    int tid = threadIdx.x;
#pragma unroll
    for (int s = tid; s < 1024; s += 256) {
        int k = s & 127, r4 = (s >> 7) * 4;
        float4 va, vb;
        va.x = g_comb[(i0 + r4 + 0) * Dd + k];
        va.y = g_comb[(i0 + r4 + 1) * Dd + k];
        va.z = g_comb[(i0 + r4 + 2) * Dd + k];
        va.w = g_comb[(i0 + r4 + 3) * Dd + k];
        *reinterpret_cast<float4*>(&AsT[k][r4]) = va;
        vb.x = g_comb[(j0 + r4 + 0) * Dd + k];
        vb.y = g_comb[(j0 + r4 + 1) * Dd + k];
        vb.z = g_comb[(j0 + r4 + 2) * Dd + k];
        vb.w = g_comb[(j0 + r4 + 3) * Dd + k];
        *reinterpret_cast<float4*>(&BsT[k][r4]) = vb;
    }
    __syncthreads();
    int tr = tid >> 4, tc = tid & 15;
    float a00 = 0.f, a01 = 0.f, a10 = 0.f, a11 = 0.f;
#pragma unroll 8
    for (int k = 0; k < 128; k++) {
        float2 a = *reinterpret_cast<const float2*>(&AsT[k][tr * 2]);
        float2 b = *reinterpret_cast<const float2*>(&BsT[k][tc * 2]);
        a00 = fmaf(a.x, b.x, a00); a01 = fmaf(a.x, b.y, a01);
        a10 = fmaf(a.y, b.x, a10); a11 = fmaf(a.y, b.y, a11);
    }
    int ri = i0 + tr * 2, rj = j0 + tc * 2;
    float ci0 = g_cn[ri], ci1 = g_cn[ri + 1], cj0 = g_cn[rj], cj1 = g_cn[rj + 1];
    float v00 = fmaxf(ci0 + cj0 - 2.f * a00, 0.f);
    float v01 = fmaxf(ci0 + cj1 - 2.f * a01, 0.f);
    float v10 = fmaxf(ci1 + cj0 - 2.f * a10, 0.f);
    float v11 = fmaxf(ci1 + cj1 - 2.f * a11, 0.f);
    g_Dc[ri * 512 + rj] = v00;       g_Dc[ri * 512 + rj + 1] = v01;
    g_Dc[(ri + 1) * 512 + rj] = v10; g_Dc[(ri + 1) * 512 + rj + 1] = v11;
    atomicAdd(&g_h16[__float_as_uint(v00) >> 16], 1u);
    atomicAdd(&g_h16[__float_as_uint(v01) >> 16], 1u);
    atomicAdd(&g_h16[__float_as_uint(v10) >> 16], 1u);
    atomicAdd(&g_h16[__float_as_uint(v11) >> 16], 1u);
}

// ---------------- decide hi16 buckets for ranks 131072, 131073 ----------------
__global__ void __launch_bounds__(1024) k_decide16() {
    __shared__ unsigned s[1024];
    int t = threadIdx.x;
    unsigned part = 0;
#pragma unroll 8
    for (int i = 0; i < 64; i++) part += g_h16[t * 64 + i];
    s[t] = part;
    __syncthreads();
    for (int off = 1; off < 1024; off <<= 1) {
        unsigned v = (t >= off) ? s[t - off] : 0u;
        __syncthreads();
        s[t] += v;
        __syncthreads();
    }
    unsigned before = (t > 0) ? s[t - 1] : 0u;
    unsigned after = s[t];
#pragma unroll
    for (int which = 0; which < 2; which++) {
        unsigned rank = 131072u + (unsigned)which;
        if (before < rank && rank <= after) {
            unsigned cum = before;
            for (int i = 0; i < 64; i++) {
                unsigned c = g_h16[t * 64 + i];
                if (cum + c >= rank) {
                    if (which == 0) { g_b1 = (unsigned)(t * 64 + i); g_rem1 = rank - cum; }
                    else            { g_b2 = (unsigned)(t * 64 + i); g_rem2 = rank - cum; }
                    break;
                }
                cum += c;
            }
        }
    }
}

// ---------------- lo16 histogram within bucket b1; min lo16 in bucket b2 ----------------
__global__ void k_histlow() {
    unsigned b1 = g_b1, b2 = g_b2;
    unsigned lm = 0xFFFFFFFFu;
    for (int id = blockIdx.x * blockDim.x + threadIdx.x; id < 512 * 512;
         id += gridDim.x * blockDim.x) {
        unsigned u = __float_as_uint(g_Dc[id]);
        unsigned hi = u >> 16;
        if (hi == b1) atomicAdd(&g_h16[65536 + (u & 0xFFFFu)], 1u);
        else if (hi == b2) lm = min(lm, u & 0xFFFFu);
    }
    for (int o = 16; o > 0; o >>= 1) lm = min(lm, __shfl_down_sync(0xffffffffu, lm, o));
    __shared__ unsigned sm[8];
    int w = threadIdx.x >> 5;
    if ((threadIdx.x & 31) == 0) sm[w] = lm;
    __syncthreads();
    if (threadIdx.x == 0) {
        unsigned m = sm[0];
        for (int i = 1; i < 8; i++) m = min(m, sm[i]);
        if (m != 0xFFFFFFFFu) atomicMin(&g_minab, m);
    }
}

// ---------------- decide lo16, compute gamma ----------------
__global__ void __launch_bounds__(1024) k_decidelow() {
    __shared__ unsigned s[1024];
    __shared__ unsigned shv[2];
    int t = threadIdx.x;
    unsigned part = 0;
#pragma unroll 8
    for (int i = 0; i < 64; i++) part += g_h16[65536 + t * 64 + i];
    s[t] = part;
    __syncthreads();
    for (int off = 1; off < 1024; off <<= 1) {
        unsigned v = (t >= off) ? s[t - off] : 0u;
        __syncthreads();
        s[t] += v;
        __syncthreads();
    }
    unsigned before = (t > 0) ? s[t - 1] : 0u;
    unsigned after = s[t];
    unsigned b1 = g_b1, b2 = g_b2;
    bool same = (b1 == b2);
    unsigned ranks[2] = { g_rem1, same ? g_rem2 : 0u };
#pragma unroll
    for (int which = 0; which < 2; which++) {
        if (which == 1 && !same) break;
        unsigned rank = ranks[which];
        if (before < rank && rank <= after) {
            unsigned cum = before;
            for (int i = 0; i < 64; i++) {
                unsigned c = g_h16[65536 + t * 64 + i];
                if (cum + c >= rank) { shv[which] = (unsigned)(t * 64 + i); break; }
                cum += c;
            }
        }
    }
    __syncthreads();
    if (t == 0) {
        unsigned v1 = (b1 << 16) | shv[0];
        unsigned v2 = same ? ((b1 << 16) | shv[1]) : ((b2 << 16) | g_minab);
        float med = 0.5f * (__uint_as_float(v1) + __uint_as_float(v2));
        float sig = med * 0.5f;
        if (sig < 1e-6f) sig = 1.0f;
        g_gval = 1.0f / (sig + EPSf);
    }
}

// ---------------- MMD kernel sums ----------------
__global__ void k_mmd() {
    float g = g_gval;
    float sxx = 0.f, syy = 0.f, sxy = 0.f;
    for (int id = blockIdx.x * blockDim.x + threadIdx.x; id < 512 * 512;
         id += gridDim.x * blockDim.x) {
        int i = id >> 9, j = id & 511;
        float e = expf(-g * g_Dc[id]);
        if (i < Bq) { if (j < Bq) sxx += e; else sxy += e; }
        else if (j >= Bq) syy += e;
    }
    __shared__ float s1[256], s2[256], s3[256];
    int t = threadIdx.x;
    s1[t] = sxx; s2[t] = syy; s3[t] = sxy;
    __syncthreads();
    for (int s = 128; s > 0; s >>= 1) {
        if (t < s) { s1[t] += s1[t + s]; s2[t] += s2[t + s]; s3[t] += s3[t + s]; }
        __syncthreads();
    }
    if (t == 0) {
        atomicAdd(&g_acc[0], s1[0]);
        atomicAdd(&g_acc[1], s2[0]);
        atomicAdd(&g_acc[2], s3[0]);
    }
}

// ---------------- top-50: sorted tile-min guided scan over Db (exact, no margin) ----
__device__ __forceinline__ void bitonic2048(ull* a, int tid) {
    for (int k = 2; k <= 2048; k <<= 1) {
        for (int j = k >> 1; j > 0; j >>= 1) {
#pragma unroll
            for (int u = 0; u < 4; u++) {
                int i = tid + u * 512;
                int ixj = i ^ j;
                if (ixj > i) {
                    bool up = ((i & k) == 0);
                    ull x = a[i], y = a[ixj];
                    if ((x > y) == up) { a[i] = y; a[ixj] = x; }
                }
            }
            __syncthreads();
        }
    }
}

__global__ void __launch_bounds__(512) k_topk(int N) {
    __shared__ ull tiles[2048];
    __shared__ ull cand[2048];
    __shared__ int cnt;
    __shared__ float curT;
    int row = blockIdx.x, tid = threadIdx.x;
    int NT = (N + 127) >> 7;
    for (int t = tid; t < 2048; t += 512) {
        tiles[t] = (t < NT)
            ? ((((ull)__float_as_uint(g_tmin[(size_t)row * NTpad + t])) << 32) | (unsigned)t)
            : ~0ull;
        cand[t] = ~0ull;
    }
    if (tid == 0) cnt = Kn;
    __syncthreads();
    bitonic2048(tiles, tid);                       // ascending (min, tile)
    const __nv_bfloat16* Drow = g_Db + (size_t)row * N;
    int slot = tid >> 7, col = tid & 127;

    // seed: 8 lowest-min tiles, unconditional (coalesced 256B per tile)
#pragma unroll
    for (int s0 = 0; s0 < 8; s0 += 4) {
        int s = s0 + slot;
        int tl = (int)(tiles[s] & 0xFFFFFFFFu);
        int n = tl * 128 + col;
        if (n < N) {
            float v = __bfloat162float(Drow[n]);
            cand[s * 128 + col] = (((ull)__float_as_uint(v)) << 32) | (unsigned)n;
        }
    }
    __syncthreads();
    bitonic2048(cand, tid);
    if (tid == 0) curT = __uint_as_float((unsigned)(cand[Kn - 1] >> 32));
    __syncthreads();
    for (int i = Kn + tid; i < 2048; i += 512) cand[i] = ~0ull;
    __syncthreads();

    for (int s0 = 8; s0 < NT; s0 += 4) {
        float T = curT;
        if (__uint_as_float((unsigned)(tiles[s0] >> 32)) > T) break;   // exact bound
        int s = s0 + slot;
        if (s < NT) {
            ull key = tiles[s];
            if (__uint_as_float((unsigned)(key >> 32)) <= T) {
                int tl = (int)(key & 0xFFFFFFFFu);
                int n = tl * 128 + col;
                if (n < N) {
                    float v = __bfloat162float(Drow[n]);
                    if (v <= T) {
                        int p = atomicAdd(&cnt, 1);
                        cand[p] = (((ull)__float_as_uint(v)) << 32) | (unsigned)n;
                    }
                }
            }
        }
        __syncthreads();
        if (cnt >= 1536) {                          // max 1535+512=2047 < 2048: safe
            bitonic2048(cand, tid);
            if (tid == 0) {
                curT = __uint_as_float((unsigned)(cand[Kn - 1] >> 32));
                cnt = Kn;
            }
            __syncthreads();
            for (int i = Kn + tid; i < 2048; i += 512) cand[i] = ~0ull;
            __syncthreads();
        }
    }
    bitonic2048(cand, tid);
    if (tid < Kn) g_post[row * Kn + tid] = (int)(cand[tid] & 0xFFFFFFFFu);
}

// ---------------- union-KL per row (exact fp32) ----------------
__global__ void k_kl(const float* __restrict__ X, const float* __restrict__ pw,
                     const int* __restrict__ pi, const int* __restrict__ qind) {
    int row = blockIdx.x, t = threadIdx.x;
    __shared__ float Tqs[Dd];
    __shared__ int cat[2 * Kn];
    __shared__ float prew[Kn], postw[Kn], l2s[Kn];
    __shared__ float pm[2 * Kn], qm[2 * Kn], mlt[2 * Kn];
    __shared__ float red[Dd];
    __shared__ float Sp, Sq;
    Tqs[t] = g_Tq[row * Dd + t];
    int qi = qind[row];
    if (t < Kn) {
        cat[t] = pi[qi * Kn + t];
        prew[t] = pw[qi * Kn + t];
        cat[Kn + t] = g_post[row * Kn + t];
    }
    __syncthreads();
    int warp = t >> 5, lane = t & 31;
    for (int k = warp; k < Kn; k += 4) {
        const float* xr = X + (size_t)cat[Kn + k] * Dd;
        float s = 0.f;
#pragma unroll
        for (int c = lane; c < Dd; c += 32) {
            float d = Tqs[c] - xr[c];
            s = fmaf(d, d, s);
        }
        for (int o = 16; o > 0; o >>= 1) s += __shfl_down_sync(0xffffffffu, s, o);
        if (lane == 0) l2s[k] = s;
    }
    __syncthreads();
    if (t == 0) {
        float mx = -FLT_MAX;
        for (int k = 0; k < Kn; k++) {
            float z = -l2s[k] * (1.f / TAUf);
            if (z > mx) mx = z;
        }
        float sm = 0.f;
        for (int k = 0; k < Kn; k++) {
            float e = expf(-l2s[k] * (1.f / TAUf) - mx);
            postw[k] = e; sm += e;
        }
        float inv = 1.f / sm;
        for (int k = 0; k < Kn; k++) postw[k] *= inv;
    }
    __syncthreads();
    if (t < 2 * Kn) {
        int id = cat[t];
        int m = 0; float pr = 0.f, qr = 0.f;
        for (int k = 0; k < 2 * Kn; k++) m += (cat[k] == id);
        for (int k = 0; k < Kn; k++) {
            if (cat[k] == id) pr += prew[k];
            if (cat[Kn + k] == id) qr += postw[k];
        }
        pm[t] = fmaxf(pr, EPSf); qm[t] = fmaxf(qr, EPSf); mlt[t] = (float)m;
    }
    __syncthreads();
    if (t == 0) {
        float a = 0.f, bs = 0.f;
        for (int m2 = 0; m2 < 2 * Kn; m2++) { a += pm[m2] / mlt[m2]; bs += qm[m2] / mlt[m2]; }
        Sp = a; Sq = bs;
    }
    __syncthreads();
    float klc = 0.f;
    if (t < 2 * Kn) {
        float p = pm[t] / Sp, q2 = qm[t] / Sq;
        klc = p * (logf(p) - logf(q2)) / mlt[t];
    }
    red[t] = klc;
    __syncthreads();
    for (int s = Dd / 2; s > 0; s >>= 1) {
        if (t < s) red[t] += red[t + s];
        __syncthreads();
    }
    if (t == 0) atomicAdd(&g_acc[4], red[0]);
}

// ---------------- finalize ----------------
__global__ void k_final(const float* __restrict__ W, const float* __restrict__ b,
                        float* __restrict__ out) {
    __shared__ float red[256];
    int t = threadIdx.x;
    float s = 0.f;
    for (int i = t; i < Dd * Dd; i += 256) { float w = W[i]; s = fmaf(w, w, s); }
    if (t < Dd) { float bv = b[t]; s = fmaf(bv, bv, s); }
    red[t] = s;
    __syncthreads();
    for (int st = 128; st > 0; st >>= 1) {
        if (t < st) red[t] += red[t + st];
        __syncthreads();
    }
    if (t == 0) {
        float reg = 0.5f * red[0];
        float inv = 1.0f / 65536.0f;
        float kxx = g_acc[0] * inv, kyy = g_acc[1] * inv, kxy = g_acc[2] * inv;
        float dist = fmaxf(kxx + kyy - 2.f * kxy, 0.f);
        float knn = g_acc[4] / 256.0f;
        float anchor = g_acc[3] / 256.0f;
        float total = dist + knn + 1e-4f * reg + anchor;
        out[0] = total; out[1] = dist; out[2] = knn; out[3] = anchor;
    }
}

// ---------------- launch ----------------
extern "C" void kernel_launch(void* const* d_in, const int* in_sizes, int n_in,
                              void* d_out, int out_size) {
    const float* q  = (const float*)d_in[0];
    const float* X  = (const float*)d_in[1];
    const float* W  = (const float*)d_in[2];
    const float* b  = (const float*)d_in[3];
    const float* pw = (const float*)d_in[4];
    const int* pi   = (const int*)d_in[5];
    const int* qi   = (const int*)d_in[6];
    const int* idx  = (const int*)d_in[7];
    int N = in_sizes[1] / Dd;                       // 200000
    if (N > NxMax) N = NxMax;
    int NT = (N + 127) / 128;

    k_convX<<<(N + 7) / 8, 256>>>(X, N);
    k_tq<<<Bq, Dd>>>(q, W, b);
    k_comb<<<512, Dd>>>(X, idx);
    dim3 gg(Bq / 128, NT);
    k_gemm<<<gg, 256>>>(N);                         // 4th launch -> ncu capture
    k_topk<<<Bq, 512>>>(N);
    dim3 dg(512 / 32, 512 / 32);
    k_dc2<<<dg, 256>>>();
    k_decide16<<<1, 1024>>>();
    k_histlow<<<256, 256>>>();
    k_decidelow<<<1, 1024>>>();
    k_mmd<<<512, 256>>>();
    k_kl<<<Bq, Dd>>>(X, pw, pi, qi);
    k_final<<<1, 256>>>(W, b, (float*)d_out);
}